// round 16
// baseline (speedup 1.0000x reference)
#include <cuda_runtime.h>
#include <cuda_fp16.h>
#include <cstdint>

// ThreeBodyLayer — round 16: R15 + intra-warp pipelined phase 2.
// Phase 2 split into 4 chunks of M=16 (2 rows x 2 pair-chunks) with a
// 2-buffer ping-pong in the same 4KB/warp h space: build(t+1) (LDS+MUFU)
// interleaves with GEMM+epilogue(t) (ldsm+HMMA+FFMA) inside one warp.
// h swizzle upgraded (hsw3 adds pair-row bit3) -> conflict-free h STS/ldsm.
// Both rows' shfl reductions interleaved once at the end. L2 prefetch of
// the group 2 iterations ahead. Everything else identical to R15.

#define FULLMASK 0xFFFFFFFFu

__device__ __forceinline__ float softplus_f(float x) {
    return fmaxf(x, 0.0f) + __logf(1.0f + __expf(-fabsf(x)));
}
__device__ __forceinline__ __half2 softplus_h2(__half2 s) {
    const __half2 nl2e = __float2half2_rn(-1.4426950408889634f);
    __half2 t = h2exp2(__hmul2(__habs2(s), nl2e));          // exp(-|s|)
    __half2 u = __hfma2(__float2half2_rn(2.0f), t, __float2half2_rn(-1.0f));
    __half2 p = __hfma2(__float2half2_rn(-0.003464f), u,
                        __float2half2_rn( 0.013468f));
    p = __hfma2(p, u, __float2half2_rn(-0.055410f));
    p = __hfma2(p, u, __float2half2_rn( 0.333045f));
    p = __hfma2(p, u, __float2half2_rn( 0.405482f));
    return __hadd2(__hmax2(s, __float2half2_rn(0.0f)), p);
}
__device__ __forceinline__ uint32_t smem_u32(const void* p) {
    uint32_t a;
    asm("{ .reg .u64 t; cvta.to.shared.u64 t, %1; cvt.u32.u64 %0, t; }"
        : "=r"(a) : "l"(p));
    return a;
}
__device__ __forceinline__ uint32_t pkhf(float a, float b) {   // hi=a, lo=b
    uint32_t r; asm("cvt.rn.f16x2.f32 %0, %1, %2;" : "=r"(r) : "f"(a), "f"(b));
    return r;
}
__device__ __forceinline__ void ldsm4(uint32_t* r, uint32_t addr) {
    asm volatile("ldmatrix.sync.aligned.m8n8.x4.shared.b16 {%0,%1,%2,%3}, [%4];"
                 : "=r"(r[0]), "=r"(r[1]), "=r"(r[2]), "=r"(r[3]) : "r"(addr));
}
__device__ __forceinline__ void mma_f16(float* c, const uint32_t* a,
                                        uint32_t b0, uint32_t b1) {
    asm volatile(
        "mma.sync.aligned.m16n8k16.row.col.f32.f16.f16.f32 "
        "{%0,%1,%2,%3}, {%4,%5,%6,%7}, {%8,%9}, {%0,%1,%2,%3};"
        : "+f"(c[0]), "+f"(c[1]), "+f"(c[2]), "+f"(c[3])
        : "r"(a[0]), "r"(a[1]), "r"(a[2]), "r"(a[3]), "r"(b0), "r"(b1));
}

// ---- SMEM layout (bytes) per 256-thread CTA ----
static constexpr int S_W1H   = 0;        // W1^T fp16, 128B swizzled rows  24576
static constexpr int S_W2    = 24576;    // W2^T fp16, same layout          4096
static constexpr int S_CAB   = 28672;    // fp16 cab x2 buffers            53248
static constexpr int CAB_BUF = 26624;    //   16 rows * 13 vecs * 128B
static constexpr int S_H     = 81920;    // h: 8 warps x 2 chunk-bufs x 2KB 32768
static constexpr int SMEM_BYTES = 114688;

static constexpr int RPG = 16;           // rows per group (divides B)

__global__ void __launch_bounds__(256, 2) three_body_kernel(
    const float* __restrict__ core,   // [B, 64]
    const float* __restrict__ ligs,   // [B, 6, 64]
    const float* __restrict__ W1,     // [192, 64]
    const float* __restrict__ b1,     // [64]
    const float* __restrict__ W2,     // [64, 32]
    const float* __restrict__ b2,     // [32]
    const float* __restrict__ W3,     // [32]
    const float* __restrict__ b3,     // [1]
    float* __restrict__ out,          // [B]
    int B)
{
    extern __shared__ unsigned char sm[];
    const uint32_t smem_base = smem_u32(sm);
    const int tid  = threadIdx.x;
    const int lane = tid & 31;
    const int wid  = tid >> 5;        // 0..7

    // ---- stage W1^T (fp16, swizzled 128B rows) ----
    for (int idx = tid; idx < 12288; idx += 256) {
        int n = idx >> 6, k = idx & 63;
        float w;
        if      (n < 64)  w = W1[(64  + k) * 64 + n];
        else if (n < 128) w = W1[(128 + k) * 64 + (n - 64)];
        else              w = W1[k * 64 + (n - 128)];
        int byte = n * 128 + ((2 * k) ^ ((n & 7) << 4));
        *reinterpret_cast<__half*>(sm + S_W1H + byte) = __float2half_rn(w);
    }
    // ---- stage W2^T (fp16, same layout) ----
    for (int idx = tid; idx < 2048; idx += 256) {
        int n = idx >> 6, k = idx & 63;
        int byte = n * 128 + ((2 * k) ^ ((n & 7) << 4));
        *reinterpret_cast<__half*>(sm + S_W2 + byte) =
            __float2half_rn(W2[k * 32 + n]);
    }

    const float b3v = b3[0];
    const int r0  = lane >> 2;            // fragment row in m16 (0..7)
    const int c0  = (lane & 3) * 2;       // fragment col pair base
    const uint32_t lsw   = (uint32_t)(lane & 7) << 4;
    const uint32_t csel  = (uint32_t)(lane >> 4) * 16;
    const uint32_t w1row = (uint32_t)(lane & 15) * 128;
    const uint32_t w1baseH = smem_base + S_W1H;
    const uint32_t w2base  = smem_base + S_W2;
    const uint32_t hbl  = smem_base + S_H + wid * 4096;
    // h swizzle with row bit3 folded in (conflict-free STS + ldsm)
    const uint32_t lsw3 = (uint32_t)((lane & 7) ^ (((lane >> 3) & 1) << 2)) << 4;

    const int pl = lane & 15;             // pair index within chunk
    const int dh = lane >> 4;             // d-half owned by this lane
    const uint32_t psw3 = (uint32_t)((pl & 7) ^ ((pl >> 3) << 2)) << 4;

    // pair (i, 6+j) for this lane in chunk c = 0,1
    int pic[2], pjc[2];
    #pragma unroll
    for (int c = 0; c < 2; c++) {
        int q = c * 16 + pl;
        int i, j;
        if (q < 30) { i = q / 5; int jj = q % 5; j = jj + (jj >= i ? 1 : 0); }
        else        { i = 0; j = 1; }
        pic[c] = i; pjc[c] = 6 + j;
    }

    const int n_groups = B / RPG;   // 2048 exact

    // ---- phase 1: layer-1 GEMMs (identical to R15) ----
    auto phase1 = [&](int rbase, char* cb) {
        if (wid < 6) {
            const int k  = wid;
            const float* xa = ligs + (size_t)(rbase + r0) * 384 + k * 64;
            const float* xb = ligs + (size_t)(rbase + r0 + 8) * 384 + k * 64;
            uint32_t af[4][4];
            #pragma unroll
            for (int kt = 0; kt < 4; kt++) {
                int c = kt * 16 + c0;
                float2 x00 = *reinterpret_cast<const float2*>(xa + c);
                float2 x10 = *reinterpret_cast<const float2*>(xb + c);
                float2 x01 = *reinterpret_cast<const float2*>(xa + c + 8);
                float2 x11 = *reinterpret_cast<const float2*>(xb + c + 8);
                af[kt][0] = pkhf(x00.y, x00.x);  af[kt][1] = pkhf(x10.y, x10.x);
                af[kt][2] = pkhf(x01.y, x01.x);  af[kt][3] = pkhf(x11.y, x11.x);
            }
            #pragma unroll
            for (int np = 0; np < 8; np++) {
                float a0[4] = {0.f, 0.f, 0.f, 0.f}, a1[4] = {0.f, 0.f, 0.f, 0.f};
                #pragma unroll
                for (int kt = 0; kt < 4; kt++) {
                    uint32_t bh[4];
                    uint32_t adr = w1baseH + (uint32_t)np * 2048 + w1row
                                 + (((uint32_t)kt * 32 + csel) ^ lsw);
                    ldsm4(bh, adr);
                    mma_f16(a0, af[kt], bh[0], bh[2]);
                    mma_f16(a1, af[kt], bh[1], bh[3]);
                }
                #pragma unroll
                for (int ntl = 0; ntl < 2; ntl++) {
                    const float* a = ntl ? a1 : a0;
                    int n = np * 16 + ntl * 8 + c0;
                    int d = n & 63;
                    int vec = (n < 64) ? k : 6 + k;
                    uint32_t v0 = pkhf(a[1], a[0]);
                    uint32_t v1 = pkhf(a[3], a[2]);
                    uint32_t off0 = (uint32_t)(2 * d)
                                  ^ ((uint32_t)((vec ^ r0) & 7) << 4);
                    uint32_t off1 = (uint32_t)(2 * d)
                                  ^ ((uint32_t)((vec ^ (r0 + 8)) & 7) << 4);
                    *reinterpret_cast<uint32_t*>(
                        cb + r0 * 1664 + vec * 128 + off0) = v0;
                    *reinterpret_cast<uint32_t*>(
                        cb + (r0 + 8) * 1664 + vec * 128 + off1) = v1;
                }
            }
        } else {
            const float* xa = core + (size_t)(rbase + r0) * 64;
            const float* xb = core + (size_t)(rbase + r0 + 8) * 64;
            uint32_t af[4][4];
            #pragma unroll
            for (int kt = 0; kt < 4; kt++) {
                int c = kt * 16 + c0;
                float2 x00 = *reinterpret_cast<const float2*>(xa + c);
                float2 x10 = *reinterpret_cast<const float2*>(xb + c);
                float2 x01 = *reinterpret_cast<const float2*>(xa + c + 8);
                float2 x11 = *reinterpret_cast<const float2*>(xb + c + 8);
                af[kt][0] = pkhf(x00.y, x00.x);  af[kt][1] = pkhf(x10.y, x10.x);
                af[kt][2] = pkhf(x01.y, x01.x);  af[kt][3] = pkhf(x11.y, x11.x);
            }
            #pragma unroll
            for (int t = 0; t < 2; t++) {
                const int np = (wid - 6) * 2 + t;
                float a0[4] = {0.f, 0.f, 0.f, 0.f}, a1[4] = {0.f, 0.f, 0.f, 0.f};
                #pragma unroll
                for (int kt = 0; kt < 4; kt++) {
                    uint32_t bh[4];
                    uint32_t adr = w1baseH + (uint32_t)(128 + np * 16) * 128 + w1row
                                 + (((uint32_t)kt * 32 + csel) ^ lsw);
                    ldsm4(bh, adr);
                    mma_f16(a0, af[kt], bh[0], bh[2]);
                    mma_f16(a1, af[kt], bh[1], bh[3]);
                }
                #pragma unroll
                for (int ntl = 0; ntl < 2; ntl++) {
                    const float* a = ntl ? a1 : a0;
                    int d = np * 16 + ntl * 8 + c0;
                    float bb0 = __ldg(b1 + d), bb1 = __ldg(b1 + d + 1);
                    uint32_t v0 = pkhf(a[1] + bb1, a[0] + bb0);
                    uint32_t v1 = pkhf(a[3] + bb1, a[2] + bb0);
                    uint32_t off0 = (uint32_t)(2 * d)
                                  ^ ((uint32_t)((12 ^ r0) & 7) << 4);
                    uint32_t off1 = (uint32_t)(2 * d)
                                  ^ ((uint32_t)((12 ^ (r0 + 8)) & 7) << 4);
                    *reinterpret_cast<uint32_t*>(
                        cb + r0 * 1664 + 12 * 128 + off0) = v0;
                    *reinterpret_cast<uint32_t*>(
                        cb + (r0 + 8) * 1664 + 12 * 128 + off1) = v1;
                }
            }
        }
    };

    // ---- L2 prefetch of a future group's x-data (no registers held) ----
    auto prefetch_l2 = [&](int rbase) {
        int r = rbase + (lane >> 2) + ((lane & 2) ? 8 : 0);
        const char* p;
        if (wid < 6)
            p = (const char*)(ligs + (size_t)r * 384 + wid * 64) + (lane & 1) * 128;
        else
            p = (const char*)(core + (size_t)r * 64) + (lane & 1) * 128;
        asm volatile("prefetch.global.L2 [%0];" :: "l"(p));
    };

    // ---- phase 2: 4 pipelined chunks of M=16 per warp ----
    auto phase2 = [&](int rbase, const char* cb) {
        float tot[2] = {0.0f, 0.0f};

        // chunk t: row = wid*2 + (t>>1), pair-chunk c = t&1, buffer = t&1
        auto build = [&](int t) {
            const int row = wid * 2 + (t >> 1);
            const int c   = t & 1;
            char* hpb = (char*)sm + S_H + wid * 4096 + (t & 1) * 2048 + pl * 128;
            const char* rowb = cb + row * 1664;
            const int vA = pic[c], vB = pjc[c];
            const char* bA = rowb + vA * 128;
            const char* bB = rowb + vB * 128;
            const char* bC = rowb + 12 * 128;
            const uint32_t swA = (uint32_t)((vA ^ row) & 7) << 4;
            const uint32_t swB = (uint32_t)((vB ^ row) & 7) << 4;
            const uint32_t swC = (uint32_t)((12 ^ row) & 7) << 4;
            #pragma unroll
            for (int v = 0; v < 4; v++) {
                const uint32_t qb = (uint32_t)(dh * 4 + v) * 16;
                uint4 ua = *reinterpret_cast<const uint4*>(bA + (qb ^ swA));
                uint4 ub = *reinterpret_cast<const uint4*>(bB + (qb ^ swB));
                uint4 uc = *reinterpret_cast<const uint4*>(bC + (qb ^ swC));
                const __half2* ha  = reinterpret_cast<const __half2*>(&ua);
                const __half2* hb2 = reinterpret_cast<const __half2*>(&ub);
                const __half2* hc  = reinterpret_cast<const __half2*>(&uc);
                uint32_t hw[4];
                #pragma unroll
                for (int w = 0; w < 4; w++) {
                    __half2 s = __hadd2(__hadd2(ha[w], hb2[w]), hc[w]);
                    __half2 r = softplus_h2(s);
                    hw[w] = *reinterpret_cast<uint32_t*>(&r);
                }
                *reinterpret_cast<uint4*>(hpb + (qb ^ psw3)) =
                    make_uint4(hw[0], hw[1], hw[2], hw[3]);
            }
        };

        auto gemm_epi = [&](int t) {
            const int c = t & 1;
            const uint32_t hb = hbl + (uint32_t)(t & 1) * 2048;
            float acc[4][4];
            #pragma unroll
            for (int nt = 0; nt < 4; nt++)
                #pragma unroll
                for (int e = 0; e < 4; e++) acc[nt][e] = 0.0f;
            #pragma unroll
            for (int kt = 0; kt < 4; kt++) {
                const uint32_t kb = (uint32_t)kt * 32 + csel;
                uint32_t afr[4], bf0[4], bf1[4];
                ldsm4(afr, hb + w1row + (kb ^ lsw3));
                ldsm4(bf0, w2base + w1row + (kb ^ lsw));
                ldsm4(bf1, w2base + 2048 + w1row + (kb ^ lsw));
                mma_f16(acc[0], afr, bf0[0], bf0[2]);
                mma_f16(acc[1], afr, bf0[1], bf0[3]);
                mma_f16(acc[2], afr, bf1[0], bf1[2]);
                mma_f16(acc[3], afr, bf1[1], bf1[3]);
            }
            float part = 0.0f;
            #pragma unroll
            for (int hf = 0; hf < 2; hf++) {
                int q = c * 16 + (lane >> 2) + hf * 8;
                if (q < 30) {
                    #pragma unroll
                    for (int nt = 0; nt < 4; nt++)
                        #pragma unroll
                        for (int e = 0; e < 2; e++) {
                            int nn = nt * 8 + c0 + e;
                            part += softplus_f(acc[nt][hf * 2 + e]
                                               + __ldg(b2 + nn)) * __ldg(W3 + nn);
                        }
                }
            }
            tot[t >> 1] += part;
        };

        build(0);
        #pragma unroll
        for (int t = 0; t < 4; t++) {
            __syncwarp();
            if (t < 3) build(t + 1);      // next chunk (LDS+MUFU stream)
            gemm_epi(t);                   // this chunk (ldsm+MMA+FFMA stream)
        }

        // both rows' reductions interleaved (two independent shfl chains)
        #pragma unroll
        for (int off = 16; off; off >>= 1) {
            tot[0] += __shfl_xor_sync(FULLMASK, tot[0], off);
            tot[1] += __shfl_xor_sync(FULLMASK, tot[1], off);
        }
        if (lane == 0) {
            out[rbase + wid * 2]     = 0.5f * tot[0] + 15.0f * b3v;
            out[rbase + wid * 2 + 1] = 0.5f * tot[1] + 15.0f * b3v;
        }
    };

    __syncthreads();   // weights staged

    // ---- pipelined main loop: 1 barrier per group ----
    char* cab = (char*)sm + S_CAB;
    int g = blockIdx.x;
    if (g < n_groups) {
        phase1(g * RPG, cab);              // prologue -> buffer 0
        int gn0 = g + gridDim.x;
        if (gn0 < n_groups) prefetch_l2(gn0 * RPG);
    }
    int it = 0;
    for (; g < n_groups; g += gridDim.x, it++) {
        __syncthreads();   // prev phase1 (buf it&1) + prev phase2 (buf (it+1)&1) done
        int gn = g + gridDim.x;
        if (gn < n_groups) phase1(gn * RPG, cab + ((it + 1) & 1) * CAB_BUF);
        int gp = g + 2 * gridDim.x;
        if (gp < n_groups) prefetch_l2(gp * RPG);
        phase2(g * RPG, cab + (it & 1) * CAB_BUF);
    }
}

extern "C" void kernel_launch(void* const* d_in, const int* in_sizes, int n_in,
                              void* d_out, int out_size) {
    const float* core = (const float*)d_in[0];
    const float* ligs = (const float*)d_in[1];
    const float* W1   = (const float*)d_in[2];
    const float* b1   = (const float*)d_in[3];
    const float* W2   = (const float*)d_in[4];
    const float* b2   = (const float*)d_in[5];
    const float* W3   = (const float*)d_in[6];
    const float* b3   = (const float*)d_in[7];
    float* out = (float*)d_out;

    const int B = in_sizes[0] / 64;   // 32768

    cudaFuncSetAttribute(three_body_kernel,
                         cudaFuncAttributeMaxDynamicSharedMemorySize, SMEM_BYTES);

    // 296 CTAs = 2 per SM (114.7KB SMEM, <=128 regs); 2048 groups of 16 rows.
    three_body_kernel<<<296, 256, SMEM_BYTES>>>(
        core, ligs, W1, b1, W2, b2, W3, b3, out, B);
}